// round 12
// baseline (speedup 1.0000x reference)
#include <cuda_runtime.h>
#include <cstdint>

#define B  8
#define N  4096
#define F  128
#define GS 1024

// Final top-k indices, jax order
__device__ int g_idx[B * GS];

__device__ __forceinline__ unsigned int monot(float v) {
    unsigned int u = __float_as_uint(v);
    return (u & 0x80000000u) ? ~u : (u | 0x80000000u); // bigger float -> bigger uint
}

// ---------------------------------------------------------------------------
// scan_hist: find bin containing the `need`-th largest (suffix scan over 256
// bins done by warp 0; 8 bins per lane).
// ---------------------------------------------------------------------------
__device__ __forceinline__ void scan_hist(const unsigned int* hist, unsigned int need,
                                          unsigned int* s_bin, unsigned int* s_above)
{
    const int tid = threadIdx.x;
    if (tid < 32) {
        unsigned int sum = 0;
        #pragma unroll
        for (int j = 0; j < 8; ++j) sum += hist[tid * 8 + j];
        unsigned int acc = sum;
        #pragma unroll
        for (int off = 1; off < 32; off <<= 1) {
            unsigned int t = __shfl_down_sync(0xFFFFFFFFu, acc, off);
            if (tid + off < 32) acc += t;
        }
        unsigned int running = acc - sum;      // strictly above my 8-bin group
        #pragma unroll
        for (int j = 7; j >= 0; --j) {
            unsigned int c = hist[tid * 8 + j];
            if (running < need && need <= running + c) {
                *s_bin = (unsigned int)(tid * 8 + j);
                *s_above = running;
            }
            running += c;
        }
    }
}

// ---------------------------------------------------------------------------
// K1: fully fused per-batch top-k. 8 CTAs x 1024 thr.
//   1. strided load of x[:, :, F-1], composite keys in registers
//   2. 256-bin histogram -> threshold bin
//   3. candidate compaction + 5 candidate-only radix passes -> exact cutoff
//   4. compact GS selected keys, bitonic sort DESC
//      (j>=32 stages in smem; j<32 stages via warp shuffles, no barriers)
//   5. write ordered indices
// composite = (u << 12) | (4095 - i): larger == earlier in jax order; unique.
// ---------------------------------------------------------------------------
__global__ __launch_bounds__(1024) void select_sort_kernel(const float* __restrict__ x)
{
    __shared__ unsigned long long cand[N];      // 32 KB (worst-case threshold bin)
    __shared__ unsigned long long stage[GS];    // 8 KB, selected keys
    __shared__ unsigned int hist[256];
    __shared__ unsigned int s_bin, s_above, s_m, s_cnt;

    const int b   = blockIdx.x;
    const int tid = threadIdx.x;

    if (tid < 256) hist[tid] = 0;
    if (tid == 0) { s_m = 0; s_cnt = 0; }
    __syncthreads();

    // Load 4 values per thread (MLP-4), build composites, histogram top-8 bits
    unsigned long long comp[4];
    #pragma unroll
    for (int l = 0; l < 4; ++l) {
        const int i = l * 1024 + tid;
        unsigned int u = monot(__ldcs(&x[((size_t)b * N + i) * F + (F - 1)]));
        comp[l] = ((unsigned long long)u << 12) | (unsigned int)(N - 1 - i);
    }
    #pragma unroll
    for (int l = 0; l < 4; ++l)
        atomicAdd(&hist[(unsigned int)(comp[l] >> 36)], 1u);
    __syncthreads();

    scan_hist(hist, GS, &s_bin, &s_above);
    __syncthreads();
    const unsigned int bin1 = s_bin;
    unsigned int need = GS - s_above;

    // Compact threshold-bin candidates
    #pragma unroll
    for (int l = 0; l < 4; ++l) {
        if ((unsigned int)(comp[l] >> 36) == bin1) {
            unsigned int p = atomicAdd(&s_m, 1u);
            cand[p] = comp[l];
        }
    }
    __syncthreads();
    const unsigned int m = s_m;

    // 5 candidate-only radix passes -> exact GS-th largest composite
    unsigned long long prefix = (unsigned long long)bin1 << 36;
    unsigned long long pmask  = 0xFFull << 36;

    #pragma unroll
    for (int pass = 0; pass < 5; ++pass) {
        const int          shift = (pass < 4) ? (28 - 8 * pass) : 0;
        const unsigned int dmask = (pass < 4) ? 0xFFu : 0xFu;

        if (tid < 256) hist[tid] = 0;
        __syncthreads();
        for (unsigned int idx = tid; idx < m; idx += 1024) {
            unsigned long long k = cand[idx];
            if ((k & pmask) == prefix)
                atomicAdd(&hist[(unsigned int)(k >> shift) & dmask], 1u);
        }
        __syncthreads();
        scan_hist(hist, need, &s_bin, &s_above);
        __syncthreads();
        prefix |= ((unsigned long long)s_bin) << shift;
        pmask  |= ((unsigned long long)dmask) << shift;
        need   -= s_above;
        __syncthreads();
    }
    // Selected set: composite >= prefix (exactly GS keys, unique).

    #pragma unroll
    for (int l = 0; l < 4; ++l) {
        if (comp[l] >= prefix) {
            unsigned int p = atomicAdd(&s_cnt, 1u);
            stage[p] = comp[l];
        }
    }
    __syncthreads();

    // Bitonic sort DESC of GS keys. Thread t owns element t.
    // j >= 32: smem compare-exchange + barrier. j < 32: register shuffles.
    for (int k = 2; k <= GS; k <<= 1) {
        for (int j = k >> 1; j >= 32; j >>= 1) {
            const int ixj = tid ^ j;
            if (ixj > tid) {
                unsigned long long a = stage[tid];
                unsigned long long c = stage[ixj];
                const bool up = ((tid & k) == 0);
                if ((a < c) == up) { stage[tid] = c; stage[ixj] = a; }
            }
            __syncthreads();
        }
        // In-register sub-warp stages (partners within the same warp)
        {
            unsigned long long v = stage[tid];
            const bool up = ((tid & k) == 0);
            const int jmax = (k >> 1 < 16) ? (k >> 1) : 16;
            #pragma unroll
            for (int j = 16; j >= 1; j >>= 1) {
                if (j <= jmax) {
                    unsigned long long p = __shfl_xor_sync(0xFFFFFFFFu, v, j);
                    const bool lower = ((tid & j) == 0);
                    const bool keep_max = (lower == up);
                    v = keep_max ? (v > p ? v : p) : (v < p ? v : p);
                }
            }
            stage[tid] = v;
            __syncthreads();
        }
    }

    g_idx[b * GS + tid] = (N - 1) - (int)(stage[tid] & 0xFFFull);
}

// ---------------------------------------------------------------------------
// K2 (R8-proven shape, sidx smem stage removed): one CTA per output row.
//   - coalesced float4 streaming load of A[b, idx[i], :] (16KB) into smem
//   - per-thread direct idx reads (L2-resident) + smem gather -> At2 row
//   - warp 0 copies x[b, idx[i], :] (512B) -> xg row
// ---------------------------------------------------------------------------
__global__ __launch_bounds__(512) void gather_kernel(const float* __restrict__ A,
                                                     const float* __restrict__ x,
                                                     float* __restrict__ out)
{
    __shared__ float row[N];        // 16 KB

    const int bi  = blockIdx.x;
    const int b   = bi >> 10;
    const int i   = bi & (GS - 1);
    const int tid = threadIdx.x;

    const int* gi = g_idx + b * GS;
    const int ri  = __ldg(&gi[i]);

    // My two column indices (coalesced, L2-resident)
    const int ci0 = __ldg(&gi[tid]);
    const int ci1 = __ldg(&gi[tid + 512]);

    const float4* arow = (const float4*)(A + ((size_t)b * N + ri) * N);
    float4* rowv = (float4*)row;
    #pragma unroll
    for (int t = tid; t < N / 4; t += 512) rowv[t] = __ldcs(&arow[t]);

    if (tid < F / 4) {
        const float4* xrow = (const float4*)(x + ((size_t)b * N + ri) * F);
        float4* xgrow = (float4*)(out + (size_t)B * GS * GS
                                      + ((size_t)b * GS + i) * F);
        xgrow[tid] = xrow[tid];
    }

    __syncthreads();

    float* orow = out + ((size_t)b * GS + i) * GS;
    orow[tid]       = row[ci0];
    orow[tid + 512] = row[ci1];
}

// ---------------------------------------------------------------------------
extern "C" void kernel_launch(void* const* d_in, const int* in_sizes, int n_in,
                              void* d_out, int out_size)
{
    const float* A = (const float*)d_in[0];  // (8,4096,4096) f32
    const float* x = (const float*)d_in[1];  // (8,4096,128)  f32
    float* out = (float*)d_out;              // At2 (8,1024,1024) ++ xg (8,1024,128)

    select_sort_kernel<<<B, 1024>>>(x);
    gather_kernel<<<B * GS, 512>>>(A, x, out);
}

// round 13
// speedup vs baseline: 1.0471x; 1.0471x over previous
#include <cuda_runtime.h>
#include <cstdint>

#define B  8
#define N  4096
#define F  128
#define GS 1024

// Final top-k indices, jax order
__device__ int g_idx[B * GS];

__device__ __forceinline__ unsigned int monot(float v) {
    unsigned int u = __float_as_uint(v);
    return (u & 0x80000000u) ? ~u : (u | 0x80000000u); // bigger float -> bigger uint
}

// ---------------------------------------------------------------------------
// scan_hist: find bin containing the `need`-th largest (suffix scan over 256
// bins done by warp 0; 8 bins per lane).
// ---------------------------------------------------------------------------
__device__ __forceinline__ void scan_hist(const unsigned int* hist, unsigned int need,
                                          unsigned int* s_bin, unsigned int* s_above)
{
    const int tid = threadIdx.x;
    if (tid < 32) {
        unsigned int sum = 0;
        #pragma unroll
        for (int j = 0; j < 8; ++j) sum += hist[tid * 8 + j];
        unsigned int acc = sum;
        #pragma unroll
        for (int off = 1; off < 32; off <<= 1) {
            unsigned int t = __shfl_down_sync(0xFFFFFFFFu, acc, off);
            if (tid + off < 32) acc += t;
        }
        unsigned int running = acc - sum;      // strictly above my 8-bin group
        #pragma unroll
        for (int j = 7; j >= 0; --j) {
            unsigned int c = hist[tid * 8 + j];
            if (running < need && need <= running + c) {
                *s_bin = (unsigned int)(tid * 8 + j);
                *s_above = running;
            }
            running += c;
        }
    }
}

// ---------------------------------------------------------------------------
// K1 (R11-proven): fully fused per-batch top-k. 8 CTAs x 1024 thr.
// composite = (u << 12) | (4095 - i): larger == earlier in jax order; unique.
// ---------------------------------------------------------------------------
__global__ __launch_bounds__(1024) void select_sort_kernel(const float* __restrict__ x)
{
    __shared__ unsigned long long cand[N];      // 32 KB (worst-case threshold bin)
    __shared__ unsigned long long stage[GS];    // 8 KB, selected keys
    __shared__ unsigned int hist[256];
    __shared__ unsigned int s_bin, s_above, s_m, s_cnt;

    const int b   = blockIdx.x;
    const int tid = threadIdx.x;

    if (tid < 256) hist[tid] = 0;
    if (tid == 0) { s_m = 0; s_cnt = 0; }
    __syncthreads();

    // Load 4 values per thread (MLP-4), build composites, histogram top-8 bits
    unsigned long long comp[4];
    #pragma unroll
    for (int l = 0; l < 4; ++l) {
        const int i = l * 1024 + tid;
        unsigned int u = monot(__ldcs(&x[((size_t)b * N + i) * F + (F - 1)]));
        comp[l] = ((unsigned long long)u << 12) | (unsigned int)(N - 1 - i);
    }
    #pragma unroll
    for (int l = 0; l < 4; ++l)
        atomicAdd(&hist[(unsigned int)(comp[l] >> 36)], 1u);
    __syncthreads();

    scan_hist(hist, GS, &s_bin, &s_above);
    __syncthreads();
    const unsigned int bin1 = s_bin;
    unsigned int need = GS - s_above;

    // Compact threshold-bin candidates
    #pragma unroll
    for (int l = 0; l < 4; ++l) {
        if ((unsigned int)(comp[l] >> 36) == bin1) {
            unsigned int p = atomicAdd(&s_m, 1u);
            cand[p] = comp[l];
        }
    }
    __syncthreads();
    const unsigned int m = s_m;

    // 5 candidate-only radix passes -> exact GS-th largest composite
    unsigned long long prefix = (unsigned long long)bin1 << 36;
    unsigned long long pmask  = 0xFFull << 36;

    #pragma unroll
    for (int pass = 0; pass < 5; ++pass) {
        const int          shift = (pass < 4) ? (28 - 8 * pass) : 0;
        const unsigned int dmask = (pass < 4) ? 0xFFu : 0xFu;

        if (tid < 256) hist[tid] = 0;
        __syncthreads();
        for (unsigned int idx = tid; idx < m; idx += 1024) {
            unsigned long long k = cand[idx];
            if ((k & pmask) == prefix)
                atomicAdd(&hist[(unsigned int)(k >> shift) & dmask], 1u);
        }
        __syncthreads();
        scan_hist(hist, need, &s_bin, &s_above);
        __syncthreads();
        prefix |= ((unsigned long long)s_bin) << shift;
        pmask  |= ((unsigned long long)dmask) << shift;
        need   -= s_above;
        __syncthreads();
    }
    // Selected set: composite >= prefix (exactly GS keys, unique).

    #pragma unroll
    for (int l = 0; l < 4; ++l) {
        if (comp[l] >= prefix) {
            unsigned int p = atomicAdd(&s_cnt, 1u);
            stage[p] = comp[l];
        }
    }
    __syncthreads();

    // Bitonic sort DESC of GS keys. Thread t owns element t.
    // j >= 32: smem compare-exchange + barrier. j < 32: register shuffles.
    for (int k = 2; k <= GS; k <<= 1) {
        for (int j = k >> 1; j >= 32; j >>= 1) {
            const int ixj = tid ^ j;
            if (ixj > tid) {
                unsigned long long a = stage[tid];
                unsigned long long c = stage[ixj];
                const bool up = ((tid & k) == 0);
                if ((a < c) == up) { stage[tid] = c; stage[ixj] = a; }
            }
            __syncthreads();
        }
        {
            unsigned long long v = stage[tid];
            const bool up = ((tid & k) == 0);
            const int jmax = (k >> 1 < 16) ? (k >> 1) : 16;
            #pragma unroll
            for (int j = 16; j >= 1; j >>= 1) {
                if (j <= jmax) {
                    unsigned long long p = __shfl_xor_sync(0xFFFFFFFFu, v, j);
                    const bool lower = ((tid & j) == 0);
                    const bool keep_max = (lower == up);
                    v = keep_max ? (v > p ? v : p) : (v < p ? v : p);
                }
            }
            stage[tid] = v;
            __syncthreads();
        }
    }

    g_idx[b * GS + tid] = (N - 1) - (int)(stage[tid] & 0xFFFull);
}

// ---------------------------------------------------------------------------
// K2: one CTA per output row, 256 threads (8 CTAs/SM -> de-phased load/gather
// across CTAs keeps DRAM reads in flight during gather phases).
//   - 4x float4 streaming loads/thread of A[b, idx[i], :] (16KB) into smem
//   - per-thread direct idx reads (L2-resident) + 4 smem gathers -> At2 row
//   - warp 0 copies x[b, idx[i], :] (512B) -> xg row
// ---------------------------------------------------------------------------
__global__ __launch_bounds__(256) void gather_kernel(const float* __restrict__ A,
                                                      const float* __restrict__ x,
                                                      float* __restrict__ out)
{
    __shared__ float row[N];        // 16 KB

    const int bi  = blockIdx.x;
    const int b   = bi >> 10;
    const int i   = bi & (GS - 1);
    const int tid = threadIdx.x;

    const int* gi = g_idx + b * GS;
    const int ri  = __ldg(&gi[i]);

    // My four column indices (coalesced, L2-resident)
    const int ci0 = __ldg(&gi[tid]);
    const int ci1 = __ldg(&gi[tid + 256]);
    const int ci2 = __ldg(&gi[tid + 512]);
    const int ci3 = __ldg(&gi[tid + 768]);

    const float4* arow = (const float4*)(A + ((size_t)b * N + ri) * N);
    float4* rowv = (float4*)row;
    rowv[tid]       = __ldcs(&arow[tid]);
    rowv[tid + 256] = __ldcs(&arow[tid + 256]);
    rowv[tid + 512] = __ldcs(&arow[tid + 512]);
    rowv[tid + 768] = __ldcs(&arow[tid + 768]);

    if (tid < F / 4) {
        const float4* xrow = (const float4*)(x + ((size_t)b * N + ri) * F);
        float4* xgrow = (float4*)(out + (size_t)B * GS * GS
                                      + ((size_t)b * GS + i) * F);
        xgrow[tid] = xrow[tid];
    }

    __syncthreads();

    float* orow = out + ((size_t)b * GS + i) * GS;
    orow[tid]       = row[ci0];
    orow[tid + 256] = row[ci1];
    orow[tid + 512] = row[ci2];
    orow[tid + 768] = row[ci3];
}

// ---------------------------------------------------------------------------
extern "C" void kernel_launch(void* const* d_in, const int* in_sizes, int n_in,
                              void* d_out, int out_size)
{
    const float* A = (const float*)d_in[0];  // (8,4096,4096) f32
    const float* x = (const float*)d_in[1];  // (8,4096,128)  f32
    float* out = (float*)d_out;              // At2 (8,1024,1024) ++ xg (8,1024,128)

    select_sort_kernel<<<B, 1024>>>(x);
    gather_kernel<<<B * GS, 256>>>(A, x, out);
}